// round 16
// baseline (speedup 1.0000x reference)
#include <cuda_runtime.h>
#include <cuda_fp16.h>
#include <math.h>
#include <stdint.h>

#define TOKENS   8192
#define DIM      4096
#define NEXP     256
#define TOPK     8
#define TOPKG    4
#define ROUTE_SCALE 2.5f
#define WSCALE   64.0f
#define RSCALE   2048.0f            // residual pre-scale (2^11) -> no fp16 subnormals
#define INV_RS   (1.0f/2048.0f)
#define INV_WSCALE (1.0f/64.0f)

#define BM 64
#define BN 256
#define KB 64                       // K elements per chunk
#define NCHUNK (DIM/KB)             // 64
#define NTHREADS 512

#define A_TILE_B (BM*KB*2)          // 8192 B
#define B_TILE_B (BN*KB*2)          // 32768 B
#define STAGE_B  (2*A_TILE_B + 2*B_TILE_B)   // 81920 B  (Ah Am Bh Bm)
#define SMEM_TOTAL (2*STAGE_B)      // 163840 B
#define SROW 260                    // score smem row stride (floats)

// ---------------- device scratch (fp16 split W only) ----------------
__device__ __half g_wh[(size_t)NEXP*DIM];     // W*64
__device__ __half g_wm[(size_t)NEXP*DIM];     // 2048*(W*64 - wh)

union Pack8h { __half h[8]; uint4 u; };

__global__ __launch_bounds__(256)
void splitw_kernel(const float* __restrict__ W) {
    const size_t WN8 = (size_t)NEXP*DIM/8;
    size_t i = (size_t)blockIdx.x*blockDim.x + threadIdx.x;
    if (i >= WN8) return;
    const float4* s4 = (const float4*)W;
    float4 v0 = s4[i*2], v1 = s4[i*2+1];
    float v[8] = {v0.x,v0.y,v0.z,v0.w,v1.x,v1.y,v1.z,v1.w};
    Pack8h ph, pm;
    #pragma unroll
    for (int j = 0; j < 8; j++) {
        float a = v[j] * WSCALE;
        __half hb = __float2half_rn(a);
        float r = (a - __half2float(hb)) * RSCALE;
        ph.h[j] = hb;
        pm.h[j] = __float2half_rn(r);
    }
    ((uint4*)g_wh)[i] = ph.u;
    ((uint4*)g_wm)[i] = pm.u;
}

// ---------------- GEMM (mma.sync fp16, in-kernel x split) + routing ----------------
__device__ __forceinline__ uint32_t smem_u32(const void* p) {
    uint32_t r;
    asm("{ .reg .u64 t; cvta.to.shared.u64 t, %1; cvt.u32.u64 %0, t; }" : "=r"(r) : "l"(p));
    return r;
}

__device__ __forceinline__ void ldsm_x4(uint32_t& r0, uint32_t& r1, uint32_t& r2, uint32_t& r3,
                                        uint32_t addr) {
    asm volatile("ldmatrix.sync.aligned.m8n8.x4.shared.b16 {%0,%1,%2,%3}, [%4];"
                 : "=r"(r0), "=r"(r1), "=r"(r2), "=r"(r3) : "r"(addr));
}

__device__ __forceinline__ void mma16816(float* c, const uint32_t* a, const uint32_t* b) {
    asm volatile("mma.sync.aligned.m16n8k16.row.col.f32.f16.f16.f32 "
                 "{%0,%1,%2,%3}, {%4,%5,%6,%7}, {%8,%9}, {%0,%1,%2,%3};"
                 : "+f"(c[0]), "+f"(c[1]), "+f"(c[2]), "+f"(c[3])
                 : "r"(a[0]), "r"(a[1]), "r"(a[2]), "r"(a[3]), "r"(b[0]), "r"(b[1]));
}

__global__ __launch_bounds__(NTHREADS, 1)
void gemm_route7_kernel(const float* __restrict__ x, const float* __restrict__ bias,
                        float* __restrict__ out, int out_size) {
    extern __shared__ __align__(1024) char smem[];
    const uint32_t sbase = smem_u32(smem);
    const int tid  = threadIdx.x;
    const int wid  = tid >> 5;
    const int lane = tid & 31;
    const int wm = wid & 3;        // warp m coord (4) -> 16 rows each
    const int wn = wid >> 2;       // warp n coord (4) -> 64 cols each
    const int bm = blockIdx.x * BM;

    const int a_r   = lane & 15;
    const int a_k   = (lane >> 4) * 16;           // bytes
    const int a_x   = (a_r & 7) * 16;
    const int b_r   = (lane & 7) + ((lane >> 4) << 3);
    const int b_k   = ((lane >> 3) & 1) * 16;     // bytes
    const int b_x   = (b_r & 7) * 16;

    // A conversion mapping: one 32B (8-float) segment per thread
    const int xrow = tid >> 3;                    // 0..63
    const int xseg = tid & 7;                     // 8 segs of 8 floats per row
    const float* xsrc = x + (size_t)(bm + xrow) * DIM + xseg * 8;
    const uint32_t asts = xrow * 128 + ((xseg * 16) ^ ((xrow & 7) * 16));

    // B loads (cp.async, unchanged from R10)
    auto load_chunkB = [&](int c, int s) {
        if (c < NCHUNK) {
            const size_t boff = (size_t)c * KB;
            const uint32_t st = sbase + s * STAGE_B;
            #pragma unroll
            for (int j = 0; j < 8; j++) {
                const int idx = tid + NTHREADS * j;
                const int v   = idx >> 11;
                const int r8  = idx & 2047;
                const int row = r8 >> 3;
                const int ch  = r8 & 7;
                const uint32_t dst = st + 2 * A_TILE_B + v * B_TILE_B + row * 128 + ((ch * 16) ^ ((row & 7) * 16));
                const __half* src = (v ? g_wm : g_wh) + boff + (size_t)row * DIM + ch * 8;
                asm volatile("cp.async.cg.shared.global [%0], [%1], 16;" :: "r"(dst), "l"(src) : "memory");
            }
        }
        asm volatile("cp.async.commit_group;" ::: "memory");
    };

    float4 rA0, rA1;                              // staged fp32 x (next chunk)
    auto ldg_a = [&](int c) {
        if (c < NCHUNK) {
            rA0 = *(const float4*)(xsrc + (size_t)c * KB);
            rA1 = *(const float4*)(xsrc + (size_t)c * KB + 4);
        }
    };
    auto sts_a = [&](int c) {
        if (c < NCHUNK) {
            const int s = c & 1;
            __half2 h01 = __floats2half2_rn(rA0.x, rA0.y);
            __half2 h23 = __floats2half2_rn(rA0.z, rA0.w);
            __half2 h45 = __floats2half2_rn(rA1.x, rA1.y);
            __half2 h67 = __floats2half2_rn(rA1.z, rA1.w);
            float2 f01 = __half22float2(h01), f23 = __half22float2(h23);
            float2 f45 = __half22float2(h45), f67 = __half22float2(h67);
            __half2 m01 = __floats2half2_rn((rA0.x - f01.x) * RSCALE, (rA0.y - f01.y) * RSCALE);
            __half2 m23 = __floats2half2_rn((rA0.z - f23.x) * RSCALE, (rA0.w - f23.y) * RSCALE);
            __half2 m45 = __floats2half2_rn((rA1.x - f45.x) * RSCALE, (rA1.y - f45.y) * RSCALE);
            __half2 m67 = __floats2half2_rn((rA1.z - f67.x) * RSCALE, (rA1.w - f67.y) * RSCALE);
            char* base = smem + s * STAGE_B;
            *(uint4*)(base + asts) = make_uint4(
                *(const uint32_t*)&h01, *(const uint32_t*)&h23,
                *(const uint32_t*)&h45, *(const uint32_t*)&h67);
            *(uint4*)(base + A_TILE_B + asts) = make_uint4(
                *(const uint32_t*)&m01, *(const uint32_t*)&m23,
                *(const uint32_t*)&m45, *(const uint32_t*)&m67);
        }
    };

    float acc1[8][4], acc2[8][4];
    #pragma unroll
    for (int j = 0; j < 8; j++)
        #pragma unroll
        for (int q = 0; q < 4; q++) { acc1[j][q] = 0.0f; acc2[j][q] = 0.0f; }

    // prologue: A(0) to smem, A(1) staged in regs, B(0), B(1) in flight
    ldg_a(0); sts_a(0);
    ldg_a(1);
    load_chunkB(0, 0);
    load_chunkB(1, 1);

    for (int c = 0; c < NCHUNK; c++) {
        const int s = c & 1;
        asm volatile("cp.async.wait_group 1;" ::: "memory");
        __syncthreads();

        sts_a(c + 1);                  // store staged A for next chunk (stage s^1)

        const uint32_t st  = sbase + s * STAGE_B;
        const uint32_t sAh = st;
        const uint32_t sAm = st + A_TILE_B;
        const uint32_t sBh = st + 2 * A_TILE_B;
        const uint32_t sBm = sBh + B_TILE_B;

        #pragma unroll
        for (int kst = 0; kst < 4; kst++) {            // 4 k16 steps per chunk
            const int bc = kst * 32;
            uint32_t ah[4], am[4], bh[8][2], bmf[8][2];
            {
                const uint32_t rofs = (wm * 16 + a_r) * 128 + ((bc + a_k) ^ a_x);
                ldsm_x4(ah[0], ah[1], ah[2], ah[3], sAh + rofs);
                ldsm_x4(am[0], am[1], am[2], am[3], sAm + rofs);
            }
            #pragma unroll
            for (int bt = 0; bt < 4; bt++) {
                const uint32_t rofs = (wn * 64 + bt * 16 + b_r) * 128 + ((bc + b_k) ^ b_x);
                ldsm_x4(bh[2*bt][0],  bh[2*bt][1],  bh[2*bt+1][0],  bh[2*bt+1][1],  sBh + rofs);
                ldsm_x4(bmf[2*bt][0], bmf[2*bt][1], bmf[2*bt+1][0], bmf[2*bt+1][1], sBm + rofs);
            }
            #pragma unroll
            for (int nt = 0; nt < 8; nt++) {
                mma16816(acc1[nt], ah, bh[nt]);    // hh -> S1
                mma16816(acc2[nt], ah, bmf[nt]);   // hm -> S2
                mma16816(acc2[nt], am, bh[nt]);    // mh -> S2
            }
        }

        __syncthreads();                 // all warps done reading stage s; A STS visible next iter
        load_chunkB(c + 2, s);
        ldg_a(c + 2);                    // stage A for chunk c+2 in regs
    }

    asm volatile("cp.async.wait_group 0;" ::: "memory");
    __syncthreads();

    // ---- scores -> smem: sigmoid((S1 + S2/2048)/64) ----
    float* sc = (float*)smem;
    {
        const int r0 = lane >> 2;
        const int c0 = (lane & 3) * 2;
        #pragma unroll
        for (int nt = 0; nt < 8; nt++) {
            const int row = wm * 16 + r0;
            const int col = wn * 64 + nt * 8 + c0;
            #pragma unroll
            for (int q = 0; q < 4; q++) {
                const float L = (acc1[nt][q] + acc2[nt][q] * INV_RS) * INV_WSCALE;
                const int rr = row + (q >> 1) * 8;
                const int cc = col + (q & 1);
                sc[rr * SROW + cc] = 1.0f / (1.0f + __expf(-L));
            }
        }
    }
    __syncthreads();

    // ---- fused routing: each warp routes 4 tokens ----
    float4 bc0 = *(const float4*)(bias + lane * 8);
    float4 bc1 = *(const float4*)(bias + lane * 8 + 4);

    for (int i = 0; i < 4; i++) {
        const int tl = wid * 4 + i;
        const int t  = bm + tl;
        const float* srow = sc + (size_t)tl * SROW;

        float sv[8], sbv[8];
        {
            float4 v0 = *(const float4*)(srow + lane * 8);
            float4 v1 = *(const float4*)(srow + lane * 8 + 4);
            sv[0]=v0.x; sv[1]=v0.y; sv[2]=v0.z; sv[3]=v0.w;
            sv[4]=v1.x; sv[5]=v1.y; sv[6]=v1.z; sv[7]=v1.w;
            sbv[0]=sv[0]+bc0.x; sbv[1]=sv[1]+bc0.y; sbv[2]=sv[2]+bc0.z; sbv[3]=sv[3]+bc0.w;
            sbv[4]=sv[4]+bc1.x; sbv[5]=sv[5]+bc1.y; sbv[6]=sv[6]+bc1.z; sbv[7]=sv[7]+bc1.w;
        }

        float a = -INFINITY, b2 = -INFINITY;
        #pragma unroll
        for (int j = 0; j < 8; j++) {
            float v = sbv[j];
            if (v > a)       { b2 = a; a = v; }
            else if (v > b2) { b2 = v; }
        }
        #pragma unroll
        for (int off = 1; off <= 2; off <<= 1) {
            float oa = __shfl_xor_sync(0xffffffffu, a, off);
            float ob = __shfl_xor_sync(0xffffffffu, b2, off);
            float mx = fmaxf(a, oa);
            float s2 = fmaxf(fminf(a, oa), fmaxf(b2, ob));
            a = mx; b2 = s2;
        }
        const float gscore = a + b2;

        float g[8];
        #pragma unroll
        for (int gg = 0; gg < 8; gg++)
            g[gg] = __shfl_sync(0xffffffffu, gscore, gg * 4);

        unsigned gmask = 0;
        #pragma unroll
        for (int r = 0; r < TOPKG; r++) {
            float bv = -INFINITY; int bi = 0;
            #pragma unroll
            for (int gg = 0; gg < 8; gg++) {
                bool sel = !((gmask >> gg) & 1u) && (g[gg] > bv);
                if (sel) { bv = g[gg]; bi = gg; }
            }
            gmask |= 1u << bi;
        }

        const bool keep = (gmask >> (lane >> 2)) & 1u;
        #pragma unroll
        for (int j = 0; j < 8; j++) sbv[j] = keep ? sbv[j] : 0.0f;

        int my_idx = 0; float my_w = 0.0f;
        #pragma unroll
        for (int r = 0; r < TOPK; r++) {
            float lv = sbv[0]; int lj = 0;
            #pragma unroll
            for (int j = 1; j < 8; j++)
                if (sbv[j] > lv) { lv = sbv[j]; lj = j; }
            float v = lv; int e = lane * 8 + lj;
            #pragma unroll
            for (int off = 16; off; off >>= 1) {
                float ov = __shfl_xor_sync(0xffffffffu, v, off);
                int   oe = __shfl_xor_sync(0xffffffffu, e, off);
                if (ov > v || (ov == v && oe < e)) { v = ov; e = oe; }
            }
            float w = 0.0f;
            if ((e >> 3) == lane) {
                const int j = e & 7;
                #pragma unroll
                for (int jj = 0; jj < 8; jj++)
                    if (jj == j) { w = sv[jj]; sbv[jj] = -INFINITY; }
            }
            w = __shfl_sync(0xffffffffu, w, e >> 3);
            if (lane == r) { my_idx = e; my_w = w; }
        }

        float wsum = (lane < TOPK) ? my_w : 0.0f;
        #pragma unroll
        for (int off = 16; off; off >>= 1)
            wsum += __shfl_xor_sync(0xffffffffu, wsum, off);

        if (lane < TOPK) {
            const float wfin = my_w / wsum * ROUTE_SCALE;
            out[(size_t)t * TOPK + lane] = wfin;
            if (out_size >= 2 * TOKENS * TOPK)
                out[(size_t)TOKENS * TOPK + (size_t)t * TOPK + lane] = (float)my_idx;
        }
    }
}

extern "C" void kernel_launch(void* const* d_in, const int* in_sizes, int n_in,
                              void* d_out, int out_size) {
    const float* x    = (const float*)d_in[0];
    const float* W    = (const float*)d_in[1];
    const float* bias = (const float*)d_in[2];

    cudaFuncSetAttribute(gemm_route7_kernel, cudaFuncAttributeMaxDynamicSharedMemorySize, SMEM_TOTAL);

    const size_t wn8 = (size_t)NEXP*DIM/8;
    splitw_kernel<<<(unsigned)((wn8 + 255) / 256), 256>>>(W);

    gemm_route7_kernel<<<TOKENS / BM, NTHREADS, SMEM_TOTAL>>>(x, bias, (float*)d_out, out_size);
}